// round 5
// baseline (speedup 1.0000x reference)
#include <cuda_runtime.h>
#include <math.h>
#include <cstdint>

#define EMAX 640000
#define NMAX 50048
#define GP 296

extern __shared__ char dynsm[];

// ---------------- device scratch ----------------
__device__ float g_h0[EMAX * 128];
__device__ float g_Pa[EMAX * 128];
__device__ float g_Pb[EMAX * 128];
__device__ float g_S[NMAX * 128];
__device__ float g_nodeW[NMAX * 128];
__device__ float g_graph[256 * 128];
__device__ int   g_cnt[NMAX];
__device__ int   g_rowptr[NMAX + 1];
__device__ int   g_cur[NMAX];
__device__ int   g_csr[EMAX];

__device__ __forceinline__ float lrelu(float x) { return x >= 0.f ? x : 0.01f * x; }

typedef unsigned long long ull;
__device__ __forceinline__ ull ffma2(ull a, ull b, ull c) {
    ull d;
    asm("fma.rn.f32x2 %0, %1, %2, %3;" : "=l"(d) : "l"(a), "l"(b), "l"(c));
    return d;
}
__device__ __forceinline__ ull dup2(float x) {
    ull d;
    asm("mov.b64 %0, {%1, %1};" : "=l"(d) : "f"(x));
    return d;
}
__device__ __forceinline__ float2 unpk(ull u) {
    float2 f;
    asm("mov.b64 {%0, %1}, %2;" : "=f"(f.x), "=f"(f.y) : "l"(u));
    return f;
}

// ---- 64x128 tile GEMM, 128 threads, 8x8 per-thread blocks ----
// As: [64][128] row-major fp32.  Ws: [128][128] k-major fp32.
__device__ __forceinline__ void gemm88(const float* __restrict__ As,
                                       const float* __restrict__ Ws,
                                       ull acc[8][4], int tx, int ty) {
    const float4* As4 = (const float4*)As;
    const int r0 = ty * 8;
#pragma unroll 2
    for (int k4 = 0; k4 < 32; k4++) {
        float4 a[8];
#pragma unroll
        for (int i = 0; i < 8; i++) a[i] = As4[(r0 + i) * 32 + k4];
#pragma unroll
        for (int kk = 0; kk < 4; kk++) {
            const float* wp = Ws + (k4 * 4 + kk) * 128 + tx * 8;
            ulonglong2 b0 = *(const ulonglong2*)wp;
            ulonglong2 b1 = *(const ulonglong2*)(wp + 4);
#pragma unroll
            for (int i = 0; i < 8; i++) {
                float av = (kk == 0) ? a[i].x : (kk == 1) ? a[i].y : (kk == 2) ? a[i].z : a[i].w;
                ull d = dup2(av);
                acc[i][0] = ffma2(d, b0.x, acc[i][0]);
                acc[i][1] = ffma2(d, b0.y, acc[i][1]);
                acc[i][2] = ffma2(d, b1.x, acc[i][2]);
                acc[i][3] = ffma2(d, b1.y, acc[i][3]);
            }
        }
    }
}

__device__ __forceinline__ void store88(float* __restrict__ Pnew, ull acc[8][4],
                                        int e0, int E, int tx, int ty) {
#pragma unroll
    for (int i = 0; i < 8; i++) {
        int e = e0 + ty * 8 + i;
        if (e < E) {
            float2 p0 = unpk(acc[i][0]), p1 = unpk(acc[i][1]);
            float2 p2 = unpk(acc[i][2]), p3 = unpk(acc[i][3]);
            float4* o = (float4*)(Pnew + (size_t)e * 128 + tx * 8);
            o[0] = make_float4(p0.x, p0.y, p1.x, p1.y);
            o[1] = make_float4(p2.x, p2.y, p3.x, p3.y);
        }
    }
}

// build A tile for rounds >= 1: lrelu(S[src] - P[rev] + h0)
__device__ __forceinline__ void build_tile(float* __restrict__ As, const float* __restrict__ S,
                                           const float* __restrict__ P, const float* __restrict__ h0,
                                           const int* __restrict__ src, const int* __restrict__ rev,
                                           int e0, int E, int tid) {
#pragma unroll 4
    for (int it = 0; it < 16; it++) {
        int slot = it * 128 + tid;
        int row = slot >> 5, k4 = slot & 31;
        int e = e0 + row;
        float4 v = make_float4(0.f, 0.f, 0.f, 0.f);
        if (e < E) {
            int sn = src[e], re = rev[e];
            float4 s4 = ((const float4*)S)[(size_t)sn * 32 + k4];
            float4 p4 = ((const float4*)P)[(size_t)re * 32 + k4];
            float4 z4 = ((const float4*)h0)[(size_t)e * 32 + k4];
            v.x = lrelu(s4.x - p4.x + z4.x);
            v.y = lrelu(s4.y - p4.y + z4.y);
            v.z = lrelu(s4.z - p4.z + z4.z);
            v.w = lrelu(s4.w - p4.w + z4.w);
        }
        ((float4*)As)[slot] = v;
    }
}

// ---------------- round kernels ----------------
__global__ void __launch_bounds__(128, 2) k_gemm(
    const float* __restrict__ S, const float* __restrict__ P, const float* __restrict__ h0,
    const float* __restrict__ W, const int* __restrict__ src, const int* __restrict__ rev,
    float* __restrict__ Pnew, int E) {
    float* sm = (float*)dynsm;
    float* Ws = sm;            // 128*128
    float* As = sm + 16384;    // 64*128
    int tid = threadIdx.x;
    int tx = tid & 15, ty = tid >> 4;

    for (int i = tid; i < 16384; i += 128) Ws[i] = W[i];

    int T = (E + 63) >> 6;
    for (int t = blockIdx.x; t < T; t += gridDim.x) {
        build_tile(As, S, P, h0, src, rev, t * 64, E, tid);
        __syncthreads();
        ull acc[8][4];
#pragma unroll
        for (int i = 0; i < 8; i++)
#pragma unroll
            for (int j = 0; j < 4; j++) acc[i][j] = 0ULL;
        gemm88(As, Ws, acc, tx, ty);
        store88(Pnew, acc, t * 64, E, tx, ty);
        __syncthreads();
    }
}

// round 0: build h0 = lrelu(nodeW[src] + ef @ Web), write h0, P0 = h0 @ W
__global__ void __launch_bounds__(128, 2) k_gemm0(
    const float* __restrict__ ef, const float* __restrict__ We, const float* __restrict__ W,
    const float* __restrict__ nodeW, const int* __restrict__ src,
    float* __restrict__ h0, float* __restrict__ Pnew, int E) {
    float* sm = (float*)dynsm;
    float* Ws = sm;             // 128*128
    float* As = sm + 16384;     // 64*128
    float* Web = sm + 24576;    // 16*128
    float* sef = sm + 26624;    // 64*16
    int tid = threadIdx.x;
    int tx = tid & 15, ty = tid >> 4;

    for (int i = tid; i < 16384; i += 128) Ws[i] = W[i];
    for (int i = tid; i < 16 * 128; i += 128) Web[i] = We[64 * 128 + i];

    int T = (E + 63) >> 6;
    for (int t = blockIdx.x; t < T; t += gridDim.x) {
        int e0 = t * 64;
        for (int f = tid; f < 64 * 16; f += 128) {
            int e = e0 + (f >> 4);
            sef[f] = (e < E) ? ef[(size_t)e0 * 16 + f] : 0.f;
        }
        __syncthreads();
#pragma unroll 2
        for (int it = 0; it < 16; it++) {
            int slot = it * 128 + tid;
            int row = slot >> 5, k4 = slot & 31;
            int e = e0 + row;
            float4 v = make_float4(0.f, 0.f, 0.f, 0.f);
            if (e < E) {
                v = ((const float4*)nodeW)[(size_t)src[e] * 32 + k4];
#pragma unroll
                for (int i = 0; i < 16; i++) {
                    float f = sef[row * 16 + i];
                    float4 w = ((const float4*)Web)[i * 32 + k4];
                    v.x += f * w.x; v.y += f * w.y; v.z += f * w.z; v.w += f * w.w;
                }
                v.x = lrelu(v.x); v.y = lrelu(v.y); v.z = lrelu(v.z); v.w = lrelu(v.w);
                ((float4*)h0)[(size_t)e * 32 + k4] = v;
            }
            ((float4*)As)[slot] = v;
        }
        __syncthreads();
        ull acc[8][4];
#pragma unroll
        for (int i = 0; i < 8; i++)
#pragma unroll
            for (int j = 0; j < 4; j++) acc[i][j] = 0ULL;
        gemm88(As, Ws, acc, tx, ty);
        store88(Pnew, acc, e0, E, tx, ty);
        __syncthreads();
    }
}

// ---------------- CSR + segment-sum ----------------
__global__ void k_zero(float4* p, int n4) {
    int i = blockIdx.x * blockDim.x + threadIdx.x;
    if (i < n4) p[i] = make_float4(0.f, 0.f, 0.f, 0.f);
}
__global__ void k_zero_int(int* p, int n) {
    int i = blockIdx.x * blockDim.x + threadIdx.x;
    if (i < n) p[i] = 0;
}
__global__ void k_count(const int* __restrict__ dst, int* __restrict__ cnt, int E) {
    int e = blockIdx.x * blockDim.x + threadIdx.x;
    if (e < E) atomicAdd(&cnt[dst[e]], 1);
}
__global__ void k_scan(const int* __restrict__ cnt, int* __restrict__ rowptr, int N) {
    __shared__ int sh[1024];
    __shared__ int carry;
    int tid = threadIdx.x;
    if (tid == 0) { carry = 0; rowptr[0] = 0; }
    __syncthreads();
    for (int base = 0; base < N; base += 1024) {
        int v = (base + tid < N) ? cnt[base + tid] : 0;
        sh[tid] = v;
        __syncthreads();
        for (int off = 1; off < 1024; off <<= 1) {
            int tv = (tid >= off) ? sh[tid - off] : 0;
            __syncthreads();
            sh[tid] += tv;
            __syncthreads();
        }
        if (base + tid < N) rowptr[base + tid + 1] = carry + sh[tid];
        __syncthreads();
        if (tid == 0) carry += sh[1023];
        __syncthreads();
    }
}
__global__ void k_copy_int(const int* a, int* b, int n) {
    int i = blockIdx.x * blockDim.x + threadIdx.x;
    if (i < n) b[i] = a[i];
}
__global__ void k_fill(const int* __restrict__ dst, int* __restrict__ cur, int* __restrict__ csr, int E) {
    int e = blockIdx.x * blockDim.x + threadIdx.x;
    if (e < E) {
        int p = atomicAdd(&cur[dst[e]], 1);
        csr[p] = e;
    }
}
__global__ void k_seg(const float* __restrict__ P, const int* __restrict__ rowptr,
                      const int* __restrict__ csr, float* __restrict__ S, int N) {
    int n = blockIdx.x;
    if (n >= N) return;
    int j = threadIdx.x;
    int b = rowptr[n], t = rowptr[n + 1];
    float s = 0.f;
    for (int i = b; i < t; i++) s += P[(size_t)csr[i] * 128 + j];
    S[(size_t)n * 128 + j] = s;
}

// ---------------- nodeW = node_feat @ W_edge[0:64,:] ----------------
__global__ void k_nodeW(const float* __restrict__ nf, const float* __restrict__ We,
                        float* __restrict__ nodeW, int N) {
    __shared__ float s[16 * 64];
    int n0 = blockIdx.x * 16;
    int j = threadIdx.x;
    for (int f = j; f < 16 * 64; f += 128) {
        int n = n0 + (f >> 6);
        s[f] = (n < N) ? nf[n * 64 + (f & 63)] : 0.f;
    }
    __syncthreads();
    float acc[16];
#pragma unroll
    for (int r = 0; r < 16; r++) acc[r] = 0.f;
    for (int i = 0; i < 64; i++) {
        float w = We[i * 128 + j];
#pragma unroll
        for (int r = 0; r < 16; r++) acc[r] += s[r * 64 + i] * w;
    }
#pragma unroll
    for (int r = 0; r < 16; r++) {
        int n = n0 + r;
        if (n < N) nodeW[n * 128 + j] = acc[r];
    }
}

// ---------------- node stage: h4 gather-sum + node MLP + graph readout ----------------
__global__ void __launch_bounds__(128, 2) k_node(
    const float* __restrict__ nf, const float* __restrict__ S3, const float* __restrict__ P3,
    const float* __restrict__ h0, const int* __restrict__ src, const int* __restrict__ rev,
    const int* __restrict__ rowptr, const int* __restrict__ csr,
    const float* __restrict__ Wn, const float* __restrict__ bn,
    const int* __restrict__ gid, float* __restrict__ graph, int N) {
    float* sm = (float*)dynsm;
    float* Wns = sm;          // 192*128
    float* xc = sm + 24576;   // 8*192
    int tid = threadIdx.x;
    for (int i = tid; i < 192 * 128; i += 128) Wns[i] = Wn[i];
    float bj = bn[tid];
    int T = (N + 7) >> 3;
    for (int tt = blockIdx.x; tt < T; tt += gridDim.x) {
        int n0 = tt * 8;
        __syncthreads();
        for (int f = tid; f < 8 * 64; f += 128) {
            int n = n0 + (f >> 6);
            xc[(f >> 6) * 192 + (f & 63)] = (n < N) ? nf[n * 64 + (f & 63)] : 0.f;
        }
        for (int r = 0; r < 8; r++) {
            int n = n0 + r;
            float m = 0.f;
            if (n < N) {
                int b = rowptr[n], e2 = rowptr[n + 1];
                for (int i = b; i < e2; i++) {
                    int e = csr[i];
                    int sn = src[e], re = rev[e];
                    m += lrelu(S3[(size_t)sn * 128 + tid] - P3[(size_t)re * 128 + tid] + h0[(size_t)e * 128 + tid]);
                }
            }
            xc[r * 192 + 64 + tid] = m;
        }
        __syncthreads();
        for (int r = 0; r < 8; r++) {
            int n = n0 + r;
            if (n >= N) break;
            float acc = bj;
#pragma unroll 8
            for (int i = 0; i < 192; i++) acc += xc[r * 192 + i] * Wns[i * 128 + tid];
            atomicAdd(&graph[gid[n] * 128 + tid], lrelu(acc));
        }
    }
}

// ---------------- MoE head ----------------
__global__ void k_moe(const float* __restrict__ graph, const float* __restrict__ extra,
                      const float* __restrict__ Wg1, const float* __restrict__ bg1,
                      const float* __restrict__ Wg2, const float* __restrict__ bg2,
                      const float* __restrict__ Wg3, const float* __restrict__ bg3,
                      const float* __restrict__ EW1, const float* __restrict__ Eb1,
                      const float* __restrict__ EW2, const float* __restrict__ Eb2,
                      const float* __restrict__ EW3, const float* __restrict__ Eb3,
                      float* __restrict__ out, int B) {
    __shared__ float sx[4][144];
    __shared__ float sh[4][128];
    __shared__ float sh2[4][128];
    __shared__ float slog[4][8];
    __shared__ float sev[4][8];
    __shared__ float red[4][4];
    int j = threadIdx.x;
    int b0 = blockIdx.x * 4;
    for (int g = 0; g < 4; g++) {
        int b = b0 + g;
        if (b < B) {
            sx[g][j] = graph[b * 128 + j];
            if (j < 16) sx[g][128 + j] = extra[b * 16 + j];
        } else {
            sx[g][j] = 0.f;
            if (j < 16) sx[g][128 + j] = 0.f;
        }
    }
    __syncthreads();
    float acc[4];
#pragma unroll
    for (int g = 0; g < 4; g++) acc[g] = bg1[j];
    for (int i = 0; i < 144; i++) {
        float w = Wg1[i * 128 + j];
#pragma unroll
        for (int g = 0; g < 4; g++) acc[g] += sx[g][i] * w;
    }
#pragma unroll
    for (int g = 0; g < 4; g++) sh[g][j] = lrelu(acc[g]);
    __syncthreads();
#pragma unroll
    for (int g = 0; g < 4; g++) acc[g] = bg2[j];
    for (int i = 0; i < 128; i++) {
        float w = Wg2[i * 128 + j];
#pragma unroll
        for (int g = 0; g < 4; g++) acc[g] += sh[g][i] * w;
    }
#pragma unroll
    for (int g = 0; g < 4; g++) sh2[g][j] = lrelu(acc[g]);
    __syncthreads();
    if (j < 32) {
        int g = j >> 3, e = j & 7;
        float lg = bg3[e];
        for (int i = 0; i < 128; i++) lg += sh2[g][i] * Wg3[i * 8 + e];
        slog[g][e] = lg;
    }
    __syncthreads();
    for (int e = 0; e < 8; e++) {
#pragma unroll
        for (int g = 0; g < 4; g++) acc[g] = Eb1[e * 128 + j];
        for (int i = 0; i < 144; i++) {
            float w = EW1[(e * 144 + i) * 128 + j];
#pragma unroll
            for (int g = 0; g < 4; g++) acc[g] += sx[g][i] * w;
        }
        __syncthreads();
#pragma unroll
        for (int g = 0; g < 4; g++) sh[g][j] = lrelu(acc[g]);
        __syncthreads();
#pragma unroll
        for (int g = 0; g < 4; g++) acc[g] = Eb2[e * 128 + j];
        for (int i = 0; i < 128; i++) {
            float w = EW2[(e * 128 + i) * 128 + j];
#pragma unroll
            for (int g = 0; g < 4; g++) acc[g] += sh[g][i] * w;
        }
        float w3 = EW3[e * 128 + j];
#pragma unroll
        for (int g = 0; g < 4; g++) {
            float t = lrelu(acc[g]) * w3;
#pragma unroll
            for (int o = 16; o > 0; o >>= 1) t += __shfl_xor_sync(0xffffffffu, t, o);
            if ((j & 31) == 0) red[g][j >> 5] = t;
        }
        __syncthreads();
        if (j < 4) sev[j][e] = red[j][0] + red[j][1] + red[j][2] + red[j][3] + Eb3[e];
        __syncthreads();
    }
    if (j < 4 && b0 + j < B) {
        float mx = -1e30f;
#pragma unroll
        for (int e = 0; e < 8; e++) mx = fmaxf(mx, slog[j][e]);
        float den = 0.f, num = 0.f;
#pragma unroll
        for (int e = 0; e < 8; e++) {
            float p = __expf(slog[j][e] - mx);
            den += p;
            num += p * sev[j][e];
        }
        out[b0 + j] = num / den;
    }
}

// ---------------- launch ----------------
extern "C" void kernel_launch(void* const* d_in, const int* in_sizes, int n_in,
                              void* d_out, int out_size) {
    const float* node_feat = (const float*)d_in[0];
    const float* edge_feat = (const float*)d_in[1];
    const int* src = (const int*)d_in[2];
    const int* dst = (const int*)d_in[3];
    const int* rev = (const int*)d_in[4];
    const int* gid = (const int*)d_in[5];
    const float* extra = (const float*)d_in[6];
    const float* W_edge = (const float*)d_in[7];
    const float* W_upd = (const float*)d_in[8];
    const float* W_node = (const float*)d_in[9];
    const float* b_node = (const float*)d_in[10];
    const float* Wg1 = (const float*)d_in[11];
    const float* bg1 = (const float*)d_in[12];
    const float* Wg2 = (const float*)d_in[13];
    const float* bg2 = (const float*)d_in[14];
    const float* Wg3 = (const float*)d_in[15];
    const float* bg3 = (const float*)d_in[16];
    const float* EW1 = (const float*)d_in[17];
    const float* Eb1 = (const float*)d_in[18];
    const float* EW2 = (const float*)d_in[19];
    const float* Eb2 = (const float*)d_in[20];
    const float* EW3 = (const float*)d_in[21];
    const float* Eb3 = (const float*)d_in[22];
    float* out = (float*)d_out;

    int N = in_sizes[0] / 64;
    int E = in_sizes[2];
    int B = in_sizes[6] / 16;

    float *pH0, *pPa, *pPb, *pS, *pNW, *pGr;
    int *pCnt, *pRP, *pCur, *pCsr;
    cudaGetSymbolAddress((void**)&pH0, g_h0);
    cudaGetSymbolAddress((void**)&pPa, g_Pa);
    cudaGetSymbolAddress((void**)&pPb, g_Pb);
    cudaGetSymbolAddress((void**)&pS, g_S);
    cudaGetSymbolAddress((void**)&pNW, g_nodeW);
    cudaGetSymbolAddress((void**)&pGr, g_graph);
    cudaGetSymbolAddress((void**)&pCnt, g_cnt);
    cudaGetSymbolAddress((void**)&pRP, g_rowptr);
    cudaGetSymbolAddress((void**)&pCur, g_cur);
    cudaGetSymbolAddress((void**)&pCsr, g_csr);

    const int SMR = 24576 * 4;                    // Ws + As            = 96 KB
    const int SM0 = (24576 + 2048 + 1024) * 4;    // + Web + sef        = 108 KB
    const int SMN = (192 * 128 + 8 * 192) * 4;    // ~102 KB
    cudaFuncSetAttribute(k_gemm, cudaFuncAttributeMaxDynamicSharedMemorySize, SMR);
    cudaFuncSetAttribute(k_gemm0, cudaFuncAttributeMaxDynamicSharedMemorySize, SM0);
    cudaFuncSetAttribute(k_node, cudaFuncAttributeMaxDynamicSharedMemorySize, SMN);

    // CSR build
    k_zero_int<<<(N + 255) / 256, 256>>>(pCnt, N);
    k_count<<<(E + 255) / 256, 256>>>(dst, pCnt, E);
    k_scan<<<1, 1024>>>(pCnt, pRP, N);
    k_copy_int<<<(N + 255) / 256, 256>>>(pRP, pCur, N);
    k_fill<<<(E + 255) / 256, 256>>>(dst, pCur, pCsr, E);

    // graph readout accumulator
    k_zero<<<(B * 32 + 255) / 256, 256>>>((float4*)pGr, B * 32);

    k_nodeW<<<(N + 15) / 16, 128>>>(node_feat, W_edge, pNW, N);

    // round 0: h0, P0 -> Pa ; S0
    k_gemm0<<<GP, 128, SM0>>>(edge_feat, W_edge, W_upd, pNW, src, pH0, pPa, E);
    k_seg<<<N, 128>>>(pPa, pRP, pCsr, pS, N);
    // round 1
    k_gemm<<<GP, 128, SMR>>>(pS, pPa, pH0, W_upd, src, rev, pPb, E);
    k_seg<<<N, 128>>>(pPb, pRP, pCsr, pS, N);
    // round 2
    k_gemm<<<GP, 128, SMR>>>(pS, pPb, pH0, W_upd, src, rev, pPa, E);
    k_seg<<<N, 128>>>(pPa, pRP, pCsr, pS, N);
    // round 3
    k_gemm<<<GP, 128, SMR>>>(pS, pPa, pH0, W_upd, src, rev, pPb, E);
    k_seg<<<N, 128>>>(pPb, pRP, pCsr, pS, N);

    // node stage + readout
    k_node<<<296, 128, SMN>>>(node_feat, pS, pPb, pH0, src, rev, pRP, pCsr,
                              W_node, b_node, gid, pGr, N);

    // MoE head
    k_moe<<<(B + 3) / 4, 128>>>(pGr, extra, Wg1, bg1, Wg2, bg2, Wg3, bg3,
                                EW1, Eb1, EW2, Eb2, EW3, Eb3, out, B);
}